// round 11
// baseline (speedup 1.0000x reference)
#include <cuda_runtime.h>
#include <math.h>
#include <stdint.h>

#define H 2048
#define G 8192
#define NBQ 8
#define NBLK 148
#define NTH 896
#define WPB 28
#define WQ 14
#define SMEM_SZ 73728        // 9*H floats (init); run uses first ~10KB

// ---------------- device state ----------------
__device__ float d_xproj[18][G];
__device__ float d_bsum[G];
__device__ float d_c[H];
__device__ float d_hb[2][H];
__device__ float d_aw1[10][H];
__device__ float d_blkpart[10][160];
__device__ int   d_xrow;
__device__ unsigned g_count = 0;
__device__ unsigned g_flag  = 0;   // init barrier only
__device__ unsigned d_hcnt  = 0;   // monotonic phase-publish counter
__device__ unsigned d_sflag = 0;
__device__ unsigned d_acnt  = 0;
__device__ unsigned d_k0, d_k1;
__device__ float d_lp, d_ent;

struct P {
  const float *enc,*wih,*bih,*whh,*bhh,*wsoft,*bsoft,*bsnl,*w1,*w2,*v;
  float* out;
};

// ---------------- scoped atomics ----------------
__device__ __forceinline__ unsigned atomAddRel(unsigned* p, unsigned v){
  unsigned old;
  asm volatile("atom.add.release.gpu.global.u32 %0,[%1],%2;"
               : "=r"(old) : "l"(p), "r"(v) : "memory");
  return old;
}
__device__ __forceinline__ unsigned ldAcq(unsigned* p){
  unsigned v;
  asm volatile("ld.acquire.gpu.global.u32 %0,[%1];" : "=r"(v) : "l"(p) : "memory");
  return v;
}
__device__ __forceinline__ void stRel(unsigned* p, unsigned v){
  asm volatile("st.release.gpu.global.u32 [%0],%1;" :: "l"(p), "r"(v) : "memory");
}
__device__ __forceinline__ void stRelax(unsigned* p, unsigned v){
  asm volatile("st.relaxed.gpu.global.u32 [%0],%1;" :: "l"(p), "r"(v) : "memory");
}

// 32B weight loads with L2 eviction hints (v8.b32 shape required on sm_103a)
__device__ __forceinline__ void ldg8_el(const float* p, float* o){
  asm volatile("ld.global.nc.L2::evict_last.v8.b32 "
               "{%0,%1,%2,%3,%4,%5,%6,%7},[%8];"
               : "=f"(o[0]),"=f"(o[1]),"=f"(o[2]),"=f"(o[3]),
                 "=f"(o[4]),"=f"(o[5]),"=f"(o[6]),"=f"(o[7])
               : "l"(p));
}
__device__ __forceinline__ void ldg8_ef(const float* p, float* o){
  asm volatile("ld.global.nc.L2::evict_first.v8.b32 "
               "{%0,%1,%2,%3,%4,%5,%6,%7},[%8];"
               : "=f"(o[0]),"=f"(o[1]),"=f"(o[2]),"=f"(o[3]),
                 "=f"(o[4]),"=f"(o[5]),"=f"(o[6]),"=f"(o[7])
               : "l"(p));
}

// ---------------- threefry2x32 (JAX partitionable) ----------------
__device__ __forceinline__ void tf2(unsigned k0, unsigned k1, unsigned x0, unsigned x1,
                                    unsigned &o0, unsigned &o1){
  unsigned ks2 = k0 ^ k1 ^ 0x1BD11BDAu;
  x0 += k0; x1 += k1;
#define RND(r) { x0 += x1; x1 = (x1<<(r))|(x1>>(32-(r))); x1 ^= x0; }
  RND(13) RND(15) RND(26) RND(6)   x0 += k1;  x1 += ks2 + 1u;
  RND(17) RND(29) RND(16) RND(24)  x0 += ks2; x1 += k0  + 2u;
  RND(13) RND(15) RND(26) RND(6)   x0 += k0;  x1 += k1  + 3u;
  RND(17) RND(29) RND(16) RND(24)  x0 += k1;  x1 += ks2 + 4u;
  RND(13) RND(15) RND(26) RND(6)   x0 += ks2; x1 += k0  + 5u;
#undef RND
  o0 = x0; o1 = x1;
}

__device__ int do_sample(int n, const float* lg){
  unsigned nk0, nk1, s0, s1;
  tf2(d_k0, d_k1, 0u, 0u, nk0, nk1);
  tf2(d_k0, d_k1, 0u, 1u, s0,  s1);
  d_k0 = nk0; d_k1 = nk1;
  const float TINY = 1.17549435e-38f;
  float best = -INFINITY; int bi = 0;
  for (int i = 0; i < n; i++){
    unsigned o0, o1;
    tf2(s0, s1, 0u, (unsigned)i, o0, o1);
    unsigned bits = o0 ^ o1;
    float f = __uint_as_float((bits >> 9) | 0x3f800000u) - 1.0f;
    float u = fmaxf(TINY, f * (1.0f - TINY) + TINY);
    float z = -logf(-logf(u)) + lg[i];
    if (z > best){ best = z; bi = i; }
  }
  float mx = lg[0];
  for (int i = 1; i < n; i++) mx = fmaxf(mx, lg[i]);
  float se = 0.f;
  for (int i = 0; i < n; i++) se += expf(lg[i] - mx);
  float lse = logf(se);
  d_lp += -(lg[bi] - mx - lse);
  float e = 0.f;
  for (int i = 0; i < n; i++){ float ls = lg[i] - mx - lse; e -= ls * expf(ls); }
  d_ent += e;
  return bi;
}

__device__ __forceinline__ float sigf(float x){ return 1.f / (1.f + expf(-x)); }

__device__ __forceinline__ float wdot(const float* __restrict__ w,
                                      const float* __restrict__ shv, int lane){
  const float4* w4 = (const float4*)w;
  const float4* h4 = (const float4*)shv;
  float a = 0.f;
#pragma unroll
  for (int t = 0; t < 16; t++){
    float4 wv = w4[lane + 32*t];
    float4 hv = h4[lane + 32*t];
    a += wv.x*hv.x + wv.y*hv.y + wv.z*hv.z + wv.w*hv.w;
  }
#pragma unroll
  for (int o = 16; o; o >>= 1) a += __shfl_xor_sync(0xffffffffu, a, o);
  return a;
}

// full-row dot with hinted 32B loads: lane covers cols [lane*8 + t*256, +8)
template<int EF>
__device__ __forceinline__ void wdot2_hint(const float* __restrict__ wA,
                                           const float* __restrict__ wB,
                                           const float* __restrict__ shh,
                                           int lane, float &sA, float &sB){
  float a0 = 0.f, a1 = 0.f;
#pragma unroll
  for (int t = 0; t < 8; t++){
    int off = lane*8 + t*256;
    float4 h0 = *(const float4*)(shh + off);
    float4 h1 = *(const float4*)(shh + off + 4);
    float wa[8], wb[8];
    if (EF){ ldg8_ef(wA + off, wa); ldg8_ef(wB + off, wb); }
    else   { ldg8_el(wA + off, wa); ldg8_el(wB + off, wb); }
    a0 += wa[0]*h0.x + wa[1]*h0.y + wa[2]*h0.z + wa[3]*h0.w
        + wa[4]*h1.x + wa[5]*h1.y + wa[6]*h1.z + wa[7]*h1.w;
    a1 += wb[0]*h0.x + wb[1]*h0.y + wb[2]*h0.z + wb[3]*h0.w
        + wb[4]*h1.x + wb[5]*h1.y + wb[6]*h1.z + wb[7]*h1.w;
  }
#pragma unroll
  for (int o = 16; o; o >>= 1){
    a0 += __shfl_xor_sync(0xffffffffu, a0, o);
    a1 += __shfl_xor_sync(0xffffffffu, a1, o);
  }
  sA = a0; sB = a1;
}

// =====================================================================
// mega phase (direct-LDG, one-sided dataflow sync)
// =====================================================================
__device__ void mega(const P& p, float* sh, int b, int tid, int wi, int lane, int hp,
                     int arow, int aidx, int attnL, int opsmp, int ub,
                     int xrow, unsigned sneed, int arcpos, unsigned spub,
                     unsigned aneed, unsigned hneed,
                     int qbase, int pbase, int abase){
  float* shh = sh;                 // H floats
  float* sg  = sh + H;             // 28 odd-warp gate sums
  float* sp2 = sh + H + 32;        // attn partials 14*16
  float* sl  = sh + H + 32 + 224;  // logits
  int*   sx  = (int*)(sh + H + 32 + 224 + 16);

  // wait for input h
  if (tid == 0){
    unsigned v;
    do { v = ldAcq(&d_hcnt); } while ((int)(v - hneed) < 0);
  }
  __syncthreads();
  for (int i = tid; i < H; i += NTH) shh[i] = __ldcg(&d_hb[hp][i]);
  __syncthreads();

  if (b > 0){
    // attn partials first (early publish path for block 0)
    if (attnL > 0){
      if (wi < 14){
        int t = (b - 1) * 14 + wi;
        if (t < H){
          float s = wdot(p.w2 + (size_t)t * H, shh, lane);
          if (lane == 0){
            float vt = p.v[t];
            for (int i = 0; i < attnL; i++)
              sp2[wi*16 + i] = tanhf(__ldcg(&d_aw1[i][t]) + s) * vt;
          }
        } else if (lane == 0){
          for (int i = 0; i < attnL; i++) sp2[wi*16 + i] = 0.f;
        }
      }
      __syncthreads();
      if (tid == 0){
        for (int i = 0; i < attnL; i++){
          float s = 0.f;
#pragma unroll
          for (int w = 0; w < 14; w++) s += sp2[w*16 + i];
          d_blkpart[i][b-1] = s;
        }
        atomAddRel(&d_acnt, 1u);
      }
    }
    // gate dots: warp pair per quad, 2 rows/warp, L2-pinned direct loads
    int k = wi >> 1;
    int q = qbase + k;
    bool odd = (wi & 1);
    bool qv = (q < H);
    float aA = 0.f, aB = 0.f;
    if (qv){
      int rA = odd ? (q + 2*H) : q;
      int rB = odd ? (q + 3*H) : (q + H);
      wdot2_hint<0>(p.whh + (size_t)rA * H, p.whh + (size_t)rB * H,
                    shh, lane, aA, aB);
    }
    // merged anchor projection (streaming) + aw1
    if (arow >= 0){
      int r0 = pbase + wi * 2;
      float s0, s1;
      wdot2_hint<1>(p.wih + (size_t)r0 * H, p.wih + (size_t)(r0 + 1) * H,
                    shh, lane, s0, s1);
      if (lane == 0){ d_xproj[arow][r0] = s0; d_xproj[arow][r0 + 1] = s1; }
    }
    if (arow != -2 && wi >= 14){
      int r = abase + (wi - 14);
      float s = wdot(p.w1 + (size_t)r * H, shh, lane);
      if (lane == 0) d_aw1[aidx][r] = s;
    }
    // publish odd-warp sums; fetch sampled row
    if (qv && odd && lane == 0){ sg[2*k] = aA; sg[2*k + 1] = aB; }
    if (xrow < 0 && tid == 0){
      unsigned v;
      do { v = ldAcq(&d_sflag); } while ((int)(v - sneed) < 0);
      sx[0] = *((volatile int*)&d_xrow);
    }
    __syncthreads();
    if (qv && !odd && lane == 0){
      int xr = (xrow < 0) ? sx[0] : xrow;
      const float* xp = d_xproj[xr];
      float gi = aA        + __ldcg(xp + q)       + d_bsum[q];
      float gf = aB        + __ldcg(xp + q + H)   + d_bsum[q + H];
      float gg = sg[2*k]   + __ldcg(xp + q + 2*H) + d_bsum[q + 2*H];
      float go = sg[2*k+1] + __ldcg(xp + q + 3*H) + d_bsum[q + 3*H];
      float c2 = sigf(gf) * d_c[q] + sigf(gi) * tanhf(gg);
      float h2 = sigf(go) * tanhf(c2);
      d_c[q] = c2;
      d_hb[hp ^ 1][q] = h2;
    }
  } else {
    // ---- block 0: control / sampling ----
    if (attnL > 0){
      if (tid == 0){
        unsigned v;
        do { v = ldAcq(&d_acnt); } while ((int)(v - aneed) < 0);
      }
      __syncthreads();
      if (wi < attnL){
        float a = 0.f;
        for (int k = lane; k < NBLK-1; k += 32) a += __ldcg(&d_blkpart[wi][k]);
#pragma unroll
        for (int o = 16; o; o >>= 1) a += __shfl_xor_sync(0xffffffffu, a, o);
        if (lane == 0) sl[wi] = a;
      }
      __syncthreads();
      if (tid == 0){
        float lg[10];
        for (int i = 0; i < attnL; i++) lg[i] = 2.5f * tanhf(sl[i] / 5.0f);
        int idx = do_sample(attnL, lg);
        d_xrow = (idx < 2) ? 0 : (10 + idx - 2);
        p.out[arcpos] = (float)idx;
        stRel(&d_sflag, spub);
      }
    } else if (opsmp){
      if (wi < NBQ){
        float a = wdot(p.wsoft + (size_t)wi * H, shh, lane);
        if (lane == 0) sl[wi] = a;
      }
      __syncthreads();
      if (tid == 0){
        float lg[NBQ];
        for (int i = 0; i < NBQ; i++){
          lg[i] = tanhf((sl[i] + p.bsoft[i]) / 5.0f);
          if (ub) lg[i] += p.bsnl[i];
        }
        int op = do_sample(NBQ, lg);
        d_xrow = 2 + op;
        p.out[arcpos] = (float)op;
        stRel(&d_sflag, spub);
      }
    }
  }

  // publish phase completion
  __syncthreads();
  if (tid == 0) atomAddRel(&d_hcnt, 1u);
}

__global__ void __launch_bounds__(NTH, 1) ctrl_kernel(P p){
  extern __shared__ float sh[];
  int tid = threadIdx.x, wi = tid >> 5, lane = tid & 31;
  int b = blockIdx.x;
  unsigned gen   = *((volatile unsigned*)&g_flag);
  unsigned sbase = *((volatile unsigned*)&d_sflag);
  unsigned abase_cnt = *((volatile unsigned*)&d_acnt);
  unsigned hbase = *((volatile unsigned*)&d_hcnt);
  unsigned sc = 0, na = 0, hphase = 0;

  int qbase = (b > 0) ? (b-1)*WQ : 0;                  // guarded by q < H
  int pbase = (b > 0) ? min((b-1)*56, G - 56) : 0;
  int awb   = (b > 0) ? min((b-1)*14, H - 14) : 0;

  // ---- init ----
  for (int i = b*NTH + tid; i < H; i += NBLK*NTH){
    d_c[i] = 0.f; d_hb[0][i] = 0.f; d_hb[1][i] = 0.f;
  }
  for (int i = b*NTH + tid; i < G; i += NBLK*NTH){
    d_bsum[i] = p.bih[i] + p.bhh[i];
    d_xproj[0][i] = 0.f;
  }
  if (b == 0 && tid == 0){
    d_k0 = 0u; d_k1 = 42u;
    d_lp = 0.f; d_ent = 0.f;
  }
  // encoder rows -> smem, project all 9 through W_ih
  {
    for (int i = tid; i < 9*H; i += NTH) sh[i] = p.enc[i];
    __syncthreads();
    int gwa = b * WPB + wi;
    for (int r = gwa; r < G; r += NBLK*WPB){
      const float4* w4 = (const float4*)(p.wih + (size_t)r * H);
      float acc[9];
#pragma unroll
      for (int e = 0; e < 9; e++) acc[e] = 0.f;
      for (int t = 0; t < 16; t++){
        float4 wv = __ldg(w4 + lane + 32*t);
#pragma unroll
        for (int e = 0; e < 9; e++){
          float4 xv = ((const float4*)sh)[e*512 + lane + 32*t];
          acc[e] += wv.x*xv.x + wv.y*xv.y + wv.z*xv.z + wv.w*xv.w;
        }
      }
      for (int e = 0; e < 9; e++){
        float a = acc[e];
#pragma unroll
        for (int o = 16; o; o >>= 1) a += __shfl_xor_sync(0xffffffffu, a, o);
        if (lane == 0) d_xproj[1 + e][r] = a;
      }
    }
  }
  // init grid barrier
  __syncthreads();
  if (tid == 0){
    unsigned target = gen + 1u;
    unsigned old = atomAddRel(&g_count, 1u);
    if (old == (unsigned)(NBLK - 1)){
      stRelax(&g_count, 0u);
      stRel(&g_flag, target);
    } else {
      unsigned v;
      do { v = ldAcq(&g_flag); } while ((int)(v - target) < 0);
    }
  }
  gen += 1u;
  __syncthreads();

  // ---- two sampler runs, 42 phases each ----
  int hp = 0;
  int p_ar = -2, p_ai = 0;
#define HNEED (hbase + 148u*hphase)
  for (int smp = 0; smp < 2; smp++){
    int ab = smp * 32;
    int ub = (smp == 0);
    mega(p, sh, b, tid, wi, lane, hp, -2, 0, 0, 0, 0, 1, 0, 0, 0, 0, HNEED,
         qbase, pbase, awb);
    hp ^= 1; hphase++;
    mega(p, sh, b, tid, wi, lane, hp, -1, 0, 0, 0, 0, 1, 0, 0, 0, 0, HNEED,
         qbase, pbase, awb);
    hp ^= 1; hphase++;
    p_ar = -1; p_ai = 1;
    for (int L = 2; L <= 9; L++){
      int base = ab + (L - 2) * 4;
      // ph1: cell (enc0) + pending proj/aw1
      mega(p, sh, b, tid, wi, lane, hp, p_ar, p_ai, 0, 0, 0, 1, 0, 0, 0, 0, HNEED,
           qbase, pbase, awb);
      hp ^= 1; hphase++;
      // ph2: cell + attn(h1); b0 samples idx0
      sc++; na++;
      mega(p, sh, b, tid, wi, lane, hp, -2, 0, L, 0, 0, -1, sbase + sc,
           base + 0, sbase + sc, abase_cnt + (NBLK-1)*na, HNEED,
           qbase, pbase, awb);
      hp ^= 1; hphase++;
      // ph3: cell + attn(h2); b0 samples idx1
      sc++; na++;
      mega(p, sh, b, tid, wi, lane, hp, -2, 0, L, 0, 0, -1, sbase + sc,
           base + 2, sbase + sc, abase_cnt + (NBLK-1)*na, HNEED,
           qbase, pbase, awb);
      hp ^= 1; hphase++;
      // ph4: cell; b0 samples op0 from h3
      sc++;
      mega(p, sh, b, tid, wi, lane, hp, -2, 0, 0, 1, ub, -1, sbase + sc,
           base + 1, sbase + sc, 0, HNEED,
           qbase, pbase, awb);
      hp ^= 1; hphase++;
      // ph5: anchor cell; b0 samples op1 from h4
      sc++;
      mega(p, sh, b, tid, wi, lane, hp, -2, 0, 0, 1, ub, -1, sbase + sc,
           base + 3, sbase + sc, 0, HNEED,
           qbase, pbase, awb);
      hp ^= 1; hphase++;
      if (L < 9){ p_ar = 10 + (L - 2); p_ai = L; }   // L=9 anchor never used
      else      { p_ar = -2; p_ai = 0; }
    }
  }
#undef HNEED

  if (b == 0 && tid == 0){
    p.out[64] = d_lp;
    p.out[65] = d_ent;
  }
}

extern "C" void kernel_launch(void* const* d_in, const int* in_sizes, int n_in,
                              void* d_out, int out_size){
  P p;
  p.enc   = (const float*)d_in[0];
  p.wih   = (const float*)d_in[1];
  p.bih   = (const float*)d_in[2];
  p.whh   = (const float*)d_in[3];
  p.bhh   = (const float*)d_in[4];
  p.wsoft = (const float*)d_in[5];
  p.bsoft = (const float*)d_in[6];
  p.bsnl  = (const float*)d_in[7];
  p.w1    = (const float*)d_in[8];
  p.w2    = (const float*)d_in[9];
  p.v     = (const float*)d_in[10];
  p.out   = (float*)d_out;
  (void)in_sizes; (void)n_in; (void)out_size;

  cudaFuncSetAttribute(ctrl_kernel, cudaFuncAttributeMaxDynamicSharedMemorySize, SMEM_SZ);
  ctrl_kernel<<<NBLK, NTH, SMEM_SZ>>>(p);
}